// round 12
// baseline (speedup 1.0000x reference)
#include <cuda_runtime.h>
#include <cuda_fp16.h>
#include <cstring>

// ---------------------------------------------------------------------------
// GNN layer:
//   out = h@A^T + mean_dst(h[src]*e)@B^T + mean_dst(h[src])@C^T + b_total
// A = lin@Ws, B = lin@Wn, C = lin@Wu folded on-device.
//
// 4 kernels, single stream, no events:
//   mega(fuse ∥ convert_h16 ∥ hist + embedded scan) -> scatter -> agg -> gemm
// Edges packed to 4B: src (16 bits) | fp16(e) (16 bits). agg loads 4 edges
// per uniform LDG.128 and keeps 4 row-gathers (LDG.128 each) in flight.
// GEMM merged: K=384 over [h|hp|hu], FFMA2, bias epilogue.
// ---------------------------------------------------------------------------

#define F 128
#define EDGES_CAP 640000
#define SCAN_N 12288            // 256 threads * 48 elems, >= n_nodes

static __device__ int      g_counts[SCAN_N + 4];   // zero-init; scan re-zeroes
static __device__ int      g_cursor[SCAN_N + 4];   // excl. prefix -> row ends
static __device__ int      g_done;                 // hist-block ticket
static __device__ unsigned g_edgep[EDGES_CAP + 8]; // packed {src|e16} dst-sorted
static __device__ uint4    g_h16v[SCAN_N * 16];    // fp16 h rows: 16 uint4/row
static __device__ float    g_hp[SCAN_N * F];       // mean(h[src]*e)
static __device__ float    g_hu[SCAN_N * F];       // mean(h[src])
static __device__ float    g_W[F * 3 * F];         // [128][384] row-major [A|B|C]
static __device__ float    g_bias[F];

// bit-cast helpers (compile to MOV)
__device__ __forceinline__ unsigned h2_to_u32(__half2 v) {
    unsigned u; memcpy(&u, &v, 4); return u;
}
__device__ __forceinline__ __half2 u32_to_h2(unsigned u) {
    __half2 v; memcpy(&v, &u, 4); return v;
}
__device__ __forceinline__ unsigned long long f2_to_u64(float2 v) {
    unsigned long long u; memcpy(&u, &v, 8); return u;
}
__device__ __forceinline__ float2 u64_to_f2(unsigned long long u) {
    float2 v; memcpy(&v, &u, 8); return v;
}
__device__ __forceinline__ unsigned long long edup_from_packed(unsigned u) {
    float ev = __half2float(__ushort_as_half((unsigned short)(u >> 16)));
    unsigned long long e2;
    asm("mov.b64 %0, {%1, %1};" : "=l"(e2) : "f"(ev));
    return e2;
}

// ---------------------------------------------------------------------------
// Embedded single-block exclusive scan over SCAN_N counts -> g_cursor.
// 256 threads, 48 elems each. Also zeroes g_counts for the next replay.
// ---------------------------------------------------------------------------
__device__ void scan_embedded(int tid) {
    __shared__ int wsum[8];
    int lane = tid & 31, wid = tid >> 5;

    int4* c4 = (int4*)g_counts;
    int4* k4 = (int4*)g_cursor;

    int v[48];
    int local = 0;
    #pragma unroll
    for (int q = 0; q < 12; q++) {
        int4 a = c4[tid * 12 + q];
        v[q * 4 + 0] = a.x; v[q * 4 + 1] = a.y;
        v[q * 4 + 2] = a.z; v[q * 4 + 3] = a.w;
        local += a.x + a.y + a.z + a.w;
    }

    int inc = local;
    #pragma unroll
    for (int d = 1; d < 32; d <<= 1) {
        int t = __shfl_up_sync(0xffffffffu, inc, d);
        if (lane >= d) inc += t;
    }
    if (lane == 31) wsum[wid] = inc;
    __syncthreads();
    if (tid == 0) {
        int run = 0;
        #pragma unroll
        for (int w = 0; w < 8; w++) { int t = wsum[w]; wsum[w] = run; run += t; }
    }
    __syncthreads();

    int run = wsum[wid] + (inc - local);
    int4 z = make_int4(0, 0, 0, 0);
    #pragma unroll
    for (int q = 0; q < 12; q++) {
        int4 o;
        o.x = run; run += v[q * 4 + 0];
        o.y = run; run += v[q * 4 + 1];
        o.z = run; run += v[q * 4 + 2];
        o.w = run; run += v[q * 4 + 3];
        k4[tid * 12 + q] = o;
        c4[tid * 12 + q] = z;              // self-zero for next replay
    }
}

// ---------------------------------------------------------------------------
// Mega kernel. Block ranges:
//   [0, F)                 : fuse weights (row n = blockIdx.x)
//   [F, F+convBlocks)      : fp32 -> fp16 conversion of h
//   [F+convBlocks, ...)    : histogram of dst (8 edges/thread); the last
//                            hist block to finish runs the embedded scan.
// ---------------------------------------------------------------------------
__global__ __launch_bounds__(256) void mega_kernel(
    const float* __restrict__ lin_w, const float* __restrict__ lin_b,
    const float* __restrict__ Ws_w, const float* __restrict__ Wn_w,
    const float* __restrict__ Wu_w,
    const float* __restrict__ Ws_b, const float* __restrict__ Wn_b,
    const float* __restrict__ Wu_b,
    const float* __restrict__ h, int nElem8, int convBlocks,
    const int* __restrict__ dst, int nE, int histBlocks)
{
    int tid = threadIdx.x;
    int b = blockIdx.x;

    if (b < F) {
        // ---- fuse weights: row b of A|B|C and bias ----
        int n = b;
        __shared__ float linrow[F];
        if (tid < F) linrow[tid] = lin_w[n * F + tid];
        __syncthreads();

        for (int cc = tid; cc < 3 * F; cc += 256) {
            int seg = cc >> 7, i = cc & 127;
            const float* Wp = (seg == 0) ? Ws_w : (seg == 1) ? Wn_w : Wu_w;
            float s = 0.f;
            #pragma unroll 8
            for (int j = 0; j < F; j++)
                s += linrow[j] * Wp[j * F + i];
            g_W[n * (3 * F) + cc] = s;
        }
        if (tid < 32) {
            float s = 0.f;
            #pragma unroll
            for (int m = 0; m < 4; m++) {
                int j = tid + m * 32;
                s += linrow[j] * (Ws_b[j] + Wn_b[j] + Wu_b[j]);
            }
            #pragma unroll
            for (int d = 16; d > 0; d >>= 1)
                s += __shfl_xor_sync(0xffffffffu, s, d);
            if (tid == 0) g_bias[n] = s + lin_b[n];
        }
    } else if (b < F + convBlocks) {
        // ---- fp16 conversion ----
        int i = (b - F) * 256 + tid;
        if (i < nElem8) {
            float4 a = *(const float4*)&h[i * 8];
            float4 c = *(const float4*)&h[i * 8 + 4];
            uint4 o;
            o.x = h2_to_u32(__floats2half2_rn(a.x, a.y));
            o.y = h2_to_u32(__floats2half2_rn(a.z, a.w));
            o.z = h2_to_u32(__floats2half2_rn(c.x, c.y));
            o.w = h2_to_u32(__floats2half2_rn(c.z, c.w));
            g_h16v[i] = o;
        }
    } else {
        // ---- histogram, 8 edges/thread ----
        int hb = b - F - convBlocks;
        int base = (hb * 256 + tid) * 8;
        if (base + 7 < nE) {
            int4 d0 = *(const int4*)&dst[base];
            int4 d1 = *(const int4*)&dst[base + 4];
            atomicAdd(&g_counts[d0.x], 1); atomicAdd(&g_counts[d0.y], 1);
            atomicAdd(&g_counts[d0.z], 1); atomicAdd(&g_counts[d0.w], 1);
            atomicAdd(&g_counts[d1.x], 1); atomicAdd(&g_counts[d1.y], 1);
            atomicAdd(&g_counts[d1.z], 1); atomicAdd(&g_counts[d1.w], 1);
        } else {
            for (int q = 0; q < 8; q++)
                if (base + q < nE) atomicAdd(&g_counts[dst[base + q]], 1);
        }

        // last hist block to finish runs the scan
        __threadfence();
        __syncthreads();
        __shared__ int ticket;
        if (tid == 0) ticket = atomicAdd(&g_done, 1);
        __syncthreads();
        if (ticket == histBlocks - 1) {
            if (tid == 0) atomicExch(&g_done, 0);   // reset for next replay
            __threadfence();
            scan_embedded(tid);
        }
    }
}

// ---------------------------------------------------------------------------
// Scatter: counting-sort edges by dst into packed u32 {src | fp16(e) << 16}.
// ---------------------------------------------------------------------------
__global__ __launch_bounds__(256) void scatter_kernel(
    const int* __restrict__ src, const int* __restrict__ dst,
    const float* __restrict__ e, int nE)
{
    int base = (blockIdx.x * blockDim.x + threadIdx.x) * 8;
    if (base + 7 < nE) {
        int4   s0 = *(const int4*)&src[base];
        int4   s1 = *(const int4*)&src[base + 4];
        int4   d0 = *(const int4*)&dst[base];
        int4   d1 = *(const int4*)&dst[base + 4];
        float4 e0 = *(const float4*)&e[base];
        float4 e1 = *(const float4*)&e[base + 4];
        unsigned q0 = (unsigned)s0.x |
            ((unsigned)__half_as_ushort(__float2half_rn(e0.x)) << 16);
        unsigned q1 = (unsigned)s0.y |
            ((unsigned)__half_as_ushort(__float2half_rn(e0.y)) << 16);
        unsigned q2 = (unsigned)s0.z |
            ((unsigned)__half_as_ushort(__float2half_rn(e0.z)) << 16);
        unsigned q3 = (unsigned)s0.w |
            ((unsigned)__half_as_ushort(__float2half_rn(e0.w)) << 16);
        unsigned q4 = (unsigned)s1.x |
            ((unsigned)__half_as_ushort(__float2half_rn(e1.x)) << 16);
        unsigned q5 = (unsigned)s1.y |
            ((unsigned)__half_as_ushort(__float2half_rn(e1.y)) << 16);
        unsigned q6 = (unsigned)s1.z |
            ((unsigned)__half_as_ushort(__float2half_rn(e1.z)) << 16);
        unsigned q7 = (unsigned)s1.w |
            ((unsigned)__half_as_ushort(__float2half_rn(e1.w)) << 16);
        g_edgep[atomicAdd(&g_cursor[d0.x], 1)] = q0;
        g_edgep[atomicAdd(&g_cursor[d0.y], 1)] = q1;
        g_edgep[atomicAdd(&g_cursor[d0.z], 1)] = q2;
        g_edgep[atomicAdd(&g_cursor[d0.w], 1)] = q3;
        g_edgep[atomicAdd(&g_cursor[d1.x], 1)] = q4;
        g_edgep[atomicAdd(&g_cursor[d1.y], 1)] = q5;
        g_edgep[atomicAdd(&g_cursor[d1.z], 1)] = q6;
        g_edgep[atomicAdd(&g_cursor[d1.w], 1)] = q7;
    } else {
        for (int q = 0; q < 8; q++) {
            int i = base + q;
            if (i < nE) {
                unsigned pv = (unsigned)src[i] |
                    ((unsigned)__half_as_ushort(__float2half_rn(e[i])) << 16);
                g_edgep[atomicAdd(&g_cursor[dst[i]], 1)] = pv;
            }
        }
    }
}

// ---------------------------------------------------------------------------
// agg: one warp per node, paired-edge half-warp layout, 8 edges/iter.
// Lanes 0-15 take even edges, 16-31 odd. Each lane gathers a uint4 (16B)
// of its edge's row -> 4 LDG.128 gathers in flight. Edge metadata: one
// uniform LDG.128 = 4 packed edges. Cross-half shuffle combine at node end.
// ---------------------------------------------------------------------------
__device__ __forceinline__ void acc_edge_u4(
    uint4 rv, unsigned long long e2,
    unsigned long long hp[4], unsigned long long hu[4])
{
    unsigned long long f0 = f2_to_u64(__half22float2(u32_to_h2(rv.x)));
    unsigned long long f1 = f2_to_u64(__half22float2(u32_to_h2(rv.y)));
    unsigned long long f2 = f2_to_u64(__half22float2(u32_to_h2(rv.z)));
    unsigned long long f3 = f2_to_u64(__half22float2(u32_to_h2(rv.w)));
    asm("fma.rn.f32x2 %0, %1, %2, %0;" : "+l"(hp[0]) : "l"(f0), "l"(e2));
    asm("fma.rn.f32x2 %0, %1, %2, %0;" : "+l"(hp[1]) : "l"(f1), "l"(e2));
    asm("fma.rn.f32x2 %0, %1, %2, %0;" : "+l"(hp[2]) : "l"(f2), "l"(e2));
    asm("fma.rn.f32x2 %0, %1, %2, %0;" : "+l"(hp[3]) : "l"(f3), "l"(e2));
    asm("add.rn.f32x2 %0, %0, %1;" : "+l"(hu[0]) : "l"(f0));
    asm("add.rn.f32x2 %0, %0, %1;" : "+l"(hu[1]) : "l"(f1));
    asm("add.rn.f32x2 %0, %0, %1;" : "+l"(hu[2]) : "l"(f2));
    asm("add.rn.f32x2 %0, %0, %1;" : "+l"(hu[3]) : "l"(f3));
}

__global__ __launch_bounds__(256) void agg_kernel(int nNodes) {
    int warp = (blockIdx.x * blockDim.x + threadIdx.x) >> 5;
    int lane = threadIdx.x & 31;
    if (warp >= nNodes) return;

    int half  = lane >> 4;          // 0: even edge of pair, 1: odd edge
    int chunk = lane & 15;          // uint4 index within the 256B row

    int beg = (warp == 0) ? 0 : g_cursor[warp - 1];
    int end = g_cursor[warp];
    int deg = end - beg;

    unsigned long long hp[4] = {0, 0, 0, 0};
    unsigned long long hu[4] = {0, 0, 0, 0};

    int j = beg;
    // align j to 4 for uint4 edge loads (half 0 handles these singles)
    while (j < end && (j & 3)) {
        if (half == 0) {
            unsigned pv = g_edgep[j];
            uint4 rv = g_h16v[(pv & 0xFFFFu) * 16 + chunk];
            acc_edge_u4(rv, edup_from_packed(pv), hp, hu);
        }
        j++;
    }
    // 8 edges per iteration: 2 uniform edge loads, 4 gathers in flight
    for (; j + 8 <= end; j += 8) {
        uint4 ea = *(const uint4*)&g_edgep[j];
        uint4 eb = *(const uint4*)&g_edgep[j + 4];
        unsigned p0 = half ? ea.y : ea.x;
        unsigned p1 = half ? ea.w : ea.z;
        unsigned p2 = half ? eb.y : eb.x;
        unsigned p3 = half ? eb.w : eb.z;
        uint4 r0 = g_h16v[(p0 & 0xFFFFu) * 16 + chunk];
        uint4 r1 = g_h16v[(p1 & 0xFFFFu) * 16 + chunk];
        uint4 r2 = g_h16v[(p2 & 0xFFFFu) * 16 + chunk];
        uint4 r3 = g_h16v[(p3 & 0xFFFFu) * 16 + chunk];
        acc_edge_u4(r0, edup_from_packed(p0), hp, hu);
        acc_edge_u4(r1, edup_from_packed(p1), hp, hu);
        acc_edge_u4(r2, edup_from_packed(p2), hp, hu);
        acc_edge_u4(r3, edup_from_packed(p3), hp, hu);
    }
    if (j + 4 <= end) {
        uint4 ea = *(const uint4*)&g_edgep[j];
        unsigned p0 = half ? ea.y : ea.x;
        unsigned p1 = half ? ea.w : ea.z;
        uint4 r0 = g_h16v[(p0 & 0xFFFFu) * 16 + chunk];
        uint4 r1 = g_h16v[(p1 & 0xFFFFu) * 16 + chunk];
        acc_edge_u4(r0, edup_from_packed(p0), hp, hu);
        acc_edge_u4(r1, edup_from_packed(p1), hp, hu);
        j += 4;
    }
    if (j + 2 <= end) {
        uint2 ea = *(const uint2*)&g_edgep[j];
        unsigned p0 = half ? ea.y : ea.x;
        uint4 r0 = g_h16v[(p0 & 0xFFFFu) * 16 + chunk];
        acc_edge_u4(r0, edup_from_packed(p0), hp, hu);
        j += 2;
    }
    if (j < end && half == 0) {
        unsigned pv = g_edgep[j];
        uint4 rv = g_h16v[(pv & 0xFFFFu) * 16 + chunk];
        acc_edge_u4(rv, edup_from_packed(pv), hp, hu);
    }

    // combine the two half-warps (same chunk, xor lane bit 4)
    #pragma unroll
    for (int q = 0; q < 4; q++) {
        unsigned long long t = __shfl_xor_sync(0xffffffffu, hp[q], 16);
        asm("add.rn.f32x2 %0, %0, %1;" : "+l"(hp[q]) : "l"(t));
        t = __shfl_xor_sync(0xffffffffu, hu[q], 16);
        asm("add.rn.f32x2 %0, %0, %1;" : "+l"(hu[q]) : "l"(t));
    }

    float inv = 1.f / (float)max(deg, 1);
    // lanes 0-15 store hp chunk; lanes 16-31 store hu chunk
    unsigned long long* accs = half ? hu : hp;
    float* dstp = half ? g_hu : g_hp;
    float2 v0 = u64_to_f2(accs[0]);
    float2 v1 = u64_to_f2(accs[1]);
    float2 v2 = u64_to_f2(accs[2]);
    float2 v3 = u64_to_f2(accs[3]);
    float4 o0 = make_float4(v0.x * inv, v0.y * inv, v1.x * inv, v1.y * inv);
    float4 o1 = make_float4(v2.x * inv, v2.y * inv, v3.x * inv, v3.y * inv);
    ((float4*)dstp)[warp * 32 + chunk * 2]     = o0;
    ((float4*)dstp)[warp * 32 + chunk * 2 + 1] = o1;
}

// ---------------------------------------------------------------------------
// Merged GEMM: out[M,128] = [h|hp|hu](Mx384) @ g_W^T + bias.
// BM=64, BK=16, 256 threads, 4x8 micro-tile, FFMA2 row pairs.
// ---------------------------------------------------------------------------
#define BM 64
#define BK 16
#define XS_LD 68

struct GemmSmem {
    float Xs[BK][XS_LD];
    float Wdup[BK][2 * F];
};

__device__ __forceinline__ void gemm_tile(
    GemmSmem& sm, const float* __restrict__ Xp, int kl, int k0abs,
    int m0, int M, int tid, int tx, int ty, unsigned long long acc[2][8])
{
    {
        int row = tid >> 2;
        int cg  = tid & 3;
        int gr  = m0 + row;
        if (gr >= M) gr = M - 1;
        float4 v = *(const float4*)&Xp[gr * F + kl + cg * 4];
        sm.Xs[cg * 4 + 0][row] = v.x;
        sm.Xs[cg * 4 + 1][row] = v.y;
        sm.Xs[cg * 4 + 2][row] = v.z;
        sm.Xs[cg * 4 + 3][row] = v.w;
    }
    {
        int n  = tid >> 1;
        int c8 = (tid & 1) * 8;
        float4 v0 = *(const float4*)&g_W[n * (3 * F) + k0abs + c8];
        float4 v1 = *(const float4*)&g_W[n * (3 * F) + k0abs + c8 + 4];
        float wv[8] = {v0.x, v0.y, v0.z, v0.w, v1.x, v1.y, v1.z, v1.w};
        #pragma unroll
        for (int q = 0; q < 8; q++)
            *(float2*)&sm.Wdup[c8 + q][2 * n] = make_float2(wv[q], wv[q]);
    }
    __syncthreads();

    #pragma unroll
    for (int k = 0; k < BK; k++) {
        ulonglong2 a2 = *(const ulonglong2*)&sm.Xs[k][ty * 4];
        unsigned long long ap0 = a2.x, ap1 = a2.y;
        #pragma unroll
        for (int m = 0; m < 8; m++) {
            unsigned long long b2 =
                *(const unsigned long long*)&sm.Wdup[k][2 * (tx + 16 * m)];
            asm("fma.rn.f32x2 %0, %1, %2, %0;" : "+l"(acc[0][m])
                : "l"(ap0), "l"(b2));
            asm("fma.rn.f32x2 %0, %1, %2, %0;" : "+l"(acc[1][m])
                : "l"(ap1), "l"(b2));
        }
    }
    __syncthreads();
}

__global__ __launch_bounds__(256) void gemm_kernel(
    const float* __restrict__ h, float* __restrict__ out, int M)
{
    __shared__ GemmSmem sm;
    int tid = threadIdx.x, tx = tid & 15, ty = tid >> 4;
    int m0 = blockIdx.x * BM;

    unsigned long long acc[2][8];
    #pragma unroll
    for (int p = 0; p < 2; p++)
        #pragma unroll
        for (int m = 0; m < 8; m++) acc[p][m] = 0ull;

    for (int kt = 0; kt < 24; kt++) {
        const float* Xp = (kt < 8) ? h : (kt < 16) ? g_hp : g_hu;
        int kl = (kt & 7) * BK;
        gemm_tile(sm, Xp, kl, kt * BK, m0, M, tid, tx, ty, acc);
    }

    #pragma unroll
    for (int p = 0; p < 2; p++) {
        int r0 = m0 + ty * 4 + p * 2;
        #pragma unroll
        for (int m = 0; m < 8; m++) {
            int col = tx + 16 * m;
            float bv = g_bias[col];
            float2 v = u64_to_f2(acc[p][m]);
            if (r0 < M)     out[r0 * F + col]       = v.x + bv;
            if (r0 + 1 < M) out[(r0 + 1) * F + col] = v.y + bv;
        }
    }
}

// ---------------------------------------------------------------------------
extern "C" void kernel_launch(void* const* d_in, const int* in_sizes, int n_in,
                              void* d_out, int out_size) {
    const float* h     = (const float*)d_in[0];
    const float* e     = (const float*)d_in[1];
    const int*   src   = (const int*)d_in[2];
    const int*   dst   = (const int*)d_in[3];
    const float* Ws_w  = (const float*)d_in[4];
    const float* Ws_b  = (const float*)d_in[5];
    const float* Wn_w  = (const float*)d_in[6];
    const float* Wn_b  = (const float*)d_in[7];
    const float* Wu_w  = (const float*)d_in[8];
    const float* Wu_b  = (const float*)d_in[9];
    const float* lin_w = (const float*)d_in[10];
    const float* lin_b = (const float*)d_in[11];
    float* out = (float*)d_out;

    int M = in_sizes[0] / F;
    int E = in_sizes[2];
    if (M > SCAN_N) M = SCAN_N;
    if (E > EDGES_CAP) E = EDGES_CAP;

    int nElem8     = (M * F) / 8;
    int convBlocks = (nElem8 + 255) / 256;
    int histBlocks = (E + 2047) / 2048;

    // 1: fuse ∥ convert ∥ hist (+ embedded scan in last hist block)
    mega_kernel<<<F + convBlocks + histBlocks, 256>>>(
        lin_w, lin_b, Ws_w, Wn_w, Wu_w, Ws_b, Wn_b, Wu_b,
        h, nElem8, convBlocks, dst, E, histBlocks);
    // 2: counting sort by dst (packed 4B edges)
    scatter_kernel<<<(E + 2047) / 2048, 256>>>(src, dst, e, E);
    // 3: per-node mean aggregation
    agg_kernel<<<(M + 7) / 8, 256>>>(M);
    // 4: fused output GEMM (profiled launch)
    gemm_kernel<<<(M + BM - 1) / BM, 256>>>(h, out, M);
}

// round 13
// speedup vs baseline: 1.3286x; 1.3286x over previous
#include <cuda_runtime.h>
#include <cuda_fp16.h>
#include <cstring>

// ---------------------------------------------------------------------------
// GNN layer:
//   out = h@A^T + mean_dst(h[src]*e)@B^T + mean_dst(h[src])@C^T + b_total
// A = lin@Ws, B = lin@Wn, C = lin@Wu folded on-device.
//
// Graph (5 kernels, 2 events):
//   legacy: mega(fuse ∥ convert_h16 ∥ hist + embedded scan) -> scatter
//           -> agg -> gemm_pu
//   s2:     gemm_h (h@A^T + bias), forked after mega, joins before gemm_pu.
// GEMM v2: k-packed FFMA2 (accumulate even/odd-k partials in f32x2, one
// horizontal add at the end). X and W tiles both row-major [row][k] in smem,
// LDS.128 along k, no transpose/duplication. BM=32 BN=64 BK=32, 64 threads,
// micro 4x8 (cols interleaved stride 8), double-buffered, 626 blocks.
// ---------------------------------------------------------------------------

#define F 128
#define EDGES_CAP 640000
#define SCAN_N 12288            // 256 threads * 48 elems, >= n_nodes

static __device__ int      g_counts[SCAN_N + 4];   // zero-init; scan re-zeroes
static __device__ int      g_cursor[SCAN_N + 4];   // excl. prefix -> row ends
static __device__ int      g_done;                 // hist-block ticket
static __device__ unsigned g_edgep[EDGES_CAP + 8]; // packed {src|e16} dst-sorted
static __device__ uint4    g_h16v[SCAN_N * 16];    // fp16 h rows: 16 uint4/row
static __device__ float    g_hp[SCAN_N * F];       // mean(h[src]*e)
static __device__ float    g_hu[SCAN_N * F];       // mean(h[src])
static __device__ float    g_W[F * 3 * F];         // [128][384] row-major [A|B|C]
static __device__ float    g_bias[F];

// bit-cast helpers (compile to MOV)
__device__ __forceinline__ unsigned h2_to_u32(__half2 v) {
    unsigned u; memcpy(&u, &v, 4); return u;
}
__device__ __forceinline__ __half2 u32_to_h2(unsigned u) {
    __half2 v; memcpy(&v, &u, 4); return v;
}
__device__ __forceinline__ unsigned long long f2_to_u64(float2 v) {
    unsigned long long u; memcpy(&u, &v, 8); return u;
}
__device__ __forceinline__ float2 u64_to_f2(unsigned long long u) {
    float2 v; memcpy(&v, &u, 8); return v;
}
__device__ __forceinline__ unsigned long long edup_from_packed(unsigned u) {
    float ev = __half2float(__ushort_as_half((unsigned short)(u >> 16)));
    unsigned long long e2;
    asm("mov.b64 %0, {%1, %1};" : "=l"(e2) : "f"(ev));
    return e2;
}

// ---------------------------------------------------------------------------
// Embedded single-block exclusive scan over SCAN_N counts -> g_cursor.
// ---------------------------------------------------------------------------
__device__ void scan_embedded(int tid) {
    __shared__ int wsum[8];
    int lane = tid & 31, wid = tid >> 5;

    int4* c4 = (int4*)g_counts;
    int4* k4 = (int4*)g_cursor;

    int v[48];
    int local = 0;
    #pragma unroll
    for (int q = 0; q < 12; q++) {
        int4 a = c4[tid * 12 + q];
        v[q * 4 + 0] = a.x; v[q * 4 + 1] = a.y;
        v[q * 4 + 2] = a.z; v[q * 4 + 3] = a.w;
        local += a.x + a.y + a.z + a.w;
    }

    int inc = local;
    #pragma unroll
    for (int d = 1; d < 32; d <<= 1) {
        int t = __shfl_up_sync(0xffffffffu, inc, d);
        if (lane >= d) inc += t;
    }
    if (lane == 31) wsum[wid] = inc;
    __syncthreads();
    if (tid == 0) {
        int run = 0;
        #pragma unroll
        for (int w = 0; w < 8; w++) { int t = wsum[w]; wsum[w] = run; run += t; }
    }
    __syncthreads();

    int run = wsum[wid] + (inc - local);
    int4 z = make_int4(0, 0, 0, 0);
    #pragma unroll
    for (int q = 0; q < 12; q++) {
        int4 o;
        o.x = run; run += v[q * 4 + 0];
        o.y = run; run += v[q * 4 + 1];
        o.z = run; run += v[q * 4 + 2];
        o.w = run; run += v[q * 4 + 3];
        k4[tid * 12 + q] = o;
        c4[tid * 12 + q] = z;              // self-zero for next replay
    }
}

// ---------------------------------------------------------------------------
// Mega kernel: fuse weights | fp16 convert | histogram (+ embedded scan).
// ---------------------------------------------------------------------------
__global__ __launch_bounds__(256) void mega_kernel(
    const float* __restrict__ lin_w, const float* __restrict__ lin_b,
    const float* __restrict__ Ws_w, const float* __restrict__ Wn_w,
    const float* __restrict__ Wu_w,
    const float* __restrict__ Ws_b, const float* __restrict__ Wn_b,
    const float* __restrict__ Wu_b,
    const float* __restrict__ h, int nElem8, int convBlocks,
    const int* __restrict__ dst, int nE, int histBlocks)
{
    int tid = threadIdx.x;
    int b = blockIdx.x;

    if (b < F) {
        int n = b;
        __shared__ float linrow[F];
        if (tid < F) linrow[tid] = lin_w[n * F + tid];
        __syncthreads();

        for (int cc = tid; cc < 3 * F; cc += 256) {
            int seg = cc >> 7, i = cc & 127;
            const float* Wp = (seg == 0) ? Ws_w : (seg == 1) ? Wn_w : Wu_w;
            float s = 0.f;
            #pragma unroll 8
            for (int j = 0; j < F; j++)
                s += linrow[j] * Wp[j * F + i];
            g_W[n * (3 * F) + cc] = s;
        }
        if (tid < 32) {
            float s = 0.f;
            #pragma unroll
            for (int m = 0; m < 4; m++) {
                int j = tid + m * 32;
                s += linrow[j] * (Ws_b[j] + Wn_b[j] + Wu_b[j]);
            }
            #pragma unroll
            for (int d = 16; d > 0; d >>= 1)
                s += __shfl_xor_sync(0xffffffffu, s, d);
            if (tid == 0) g_bias[n] = s + lin_b[n];
        }
    } else if (b < F + convBlocks) {
        int i = (b - F) * 256 + tid;
        if (i < nElem8) {
            float4 a = *(const float4*)&h[i * 8];
            float4 c = *(const float4*)&h[i * 8 + 4];
            uint4 o;
            o.x = h2_to_u32(__floats2half2_rn(a.x, a.y));
            o.y = h2_to_u32(__floats2half2_rn(a.z, a.w));
            o.z = h2_to_u32(__floats2half2_rn(c.x, c.y));
            o.w = h2_to_u32(__floats2half2_rn(c.z, c.w));
            g_h16v[i] = o;
        }
    } else {
        int hb = b - F - convBlocks;
        int base = (hb * 256 + tid) * 8;
        if (base + 7 < nE) {
            int4 d0 = *(const int4*)&dst[base];
            int4 d1 = *(const int4*)&dst[base + 4];
            atomicAdd(&g_counts[d0.x], 1); atomicAdd(&g_counts[d0.y], 1);
            atomicAdd(&g_counts[d0.z], 1); atomicAdd(&g_counts[d0.w], 1);
            atomicAdd(&g_counts[d1.x], 1); atomicAdd(&g_counts[d1.y], 1);
            atomicAdd(&g_counts[d1.z], 1); atomicAdd(&g_counts[d1.w], 1);
        } else {
            for (int q = 0; q < 8; q++)
                if (base + q < nE) atomicAdd(&g_counts[dst[base + q]], 1);
        }

        __threadfence();
        __syncthreads();
        __shared__ int ticket;
        if (tid == 0) ticket = atomicAdd(&g_done, 1);
        __syncthreads();
        if (ticket == histBlocks - 1) {
            if (tid == 0) atomicExch(&g_done, 0);
            __threadfence();
            scan_embedded(tid);
        }
    }
}

// ---------------------------------------------------------------------------
// Scatter: counting-sort edges by dst into packed u32 {src | fp16(e) << 16}.
// ---------------------------------------------------------------------------
__global__ __launch_bounds__(256) void scatter_kernel(
    const int* __restrict__ src, const int* __restrict__ dst,
    const float* __restrict__ e, int nE)
{
    int base = (blockIdx.x * blockDim.x + threadIdx.x) * 8;
    if (base + 7 < nE) {
        int4   s0 = *(const int4*)&src[base];
        int4   s1 = *(const int4*)&src[base + 4];
        int4   d0 = *(const int4*)&dst[base];
        int4   d1 = *(const int4*)&dst[base + 4];
        float4 e0 = *(const float4*)&e[base];
        float4 e1 = *(const float4*)&e[base + 4];
        unsigned q0 = (unsigned)s0.x |
            ((unsigned)__half_as_ushort(__float2half_rn(e0.x)) << 16);
        unsigned q1 = (unsigned)s0.y |
            ((unsigned)__half_as_ushort(__float2half_rn(e0.y)) << 16);
        unsigned q2 = (unsigned)s0.z |
            ((unsigned)__half_as_ushort(__float2half_rn(e0.z)) << 16);
        unsigned q3 = (unsigned)s0.w |
            ((unsigned)__half_as_ushort(__float2half_rn(e0.w)) << 16);
        unsigned q4 = (unsigned)s1.x |
            ((unsigned)__half_as_ushort(__float2half_rn(e1.x)) << 16);
        unsigned q5 = (unsigned)s1.y |
            ((unsigned)__half_as_ushort(__float2half_rn(e1.y)) << 16);
        unsigned q6 = (unsigned)s1.z |
            ((unsigned)__half_as_ushort(__float2half_rn(e1.z)) << 16);
        unsigned q7 = (unsigned)s1.w |
            ((unsigned)__half_as_ushort(__float2half_rn(e1.w)) << 16);
        g_edgep[atomicAdd(&g_cursor[d0.x], 1)] = q0;
        g_edgep[atomicAdd(&g_cursor[d0.y], 1)] = q1;
        g_edgep[atomicAdd(&g_cursor[d0.z], 1)] = q2;
        g_edgep[atomicAdd(&g_cursor[d0.w], 1)] = q3;
        g_edgep[atomicAdd(&g_cursor[d1.x], 1)] = q4;
        g_edgep[atomicAdd(&g_cursor[d1.y], 1)] = q5;
        g_edgep[atomicAdd(&g_cursor[d1.z], 1)] = q6;
        g_edgep[atomicAdd(&g_cursor[d1.w], 1)] = q7;
    } else {
        for (int q = 0; q < 8; q++) {
            int i = base + q;
            if (i < nE) {
                unsigned pv = (unsigned)src[i] |
                    ((unsigned)__half_as_ushort(__float2half_rn(e[i])) << 16);
                g_edgep[atomicAdd(&g_cursor[dst[i]], 1)] = pv;
            }
        }
    }
}

// ---------------------------------------------------------------------------
// agg: warp per node, paired-edge half-warp layout, 8 edges/iter.
// ---------------------------------------------------------------------------
__device__ __forceinline__ void acc_edge_u4(
    uint4 rv, unsigned long long e2,
    unsigned long long hp[4], unsigned long long hu[4])
{
    unsigned long long f0 = f2_to_u64(__half22float2(u32_to_h2(rv.x)));
    unsigned long long f1 = f2_to_u64(__half22float2(u32_to_h2(rv.y)));
    unsigned long long f2 = f2_to_u64(__half22float2(u32_to_h2(rv.z)));
    unsigned long long f3 = f2_to_u64(__half22float2(u32_to_h2(rv.w)));
    asm("fma.rn.f32x2 %0, %1, %2, %0;" : "+l"(hp[0]) : "l"(f0), "l"(e2));
    asm("fma.rn.f32x2 %0, %1, %2, %0;" : "+l"(hp[1]) : "l"(f1), "l"(e2));
    asm("fma.rn.f32x2 %0, %1, %2, %0;" : "+l"(hp[2]) : "l"(f2), "l"(e2));
    asm("fma.rn.f32x2 %0, %1, %2, %0;" : "+l"(hp[3]) : "l"(f3), "l"(e2));
    asm("add.rn.f32x2 %0, %0, %1;" : "+l"(hu[0]) : "l"(f0));
    asm("add.rn.f32x2 %0, %0, %1;" : "+l"(hu[1]) : "l"(f1));
    asm("add.rn.f32x2 %0, %0, %1;" : "+l"(hu[2]) : "l"(f2));
    asm("add.rn.f32x2 %0, %0, %1;" : "+l"(hu[3]) : "l"(f3));
}

__global__ __launch_bounds__(256) void agg_kernel(int nNodes) {
    int warp = (blockIdx.x * blockDim.x + threadIdx.x) >> 5;
    int lane = threadIdx.x & 31;
    if (warp >= nNodes) return;

    int half  = lane >> 4;
    int chunk = lane & 15;

    int beg = (warp == 0) ? 0 : g_cursor[warp - 1];
    int end = g_cursor[warp];
    int deg = end - beg;

    unsigned long long hp[4] = {0, 0, 0, 0};
    unsigned long long hu[4] = {0, 0, 0, 0};

    int j = beg;
    while (j < end && (j & 3)) {
        if (half == 0) {
            unsigned pv = g_edgep[j];
            uint4 rv = g_h16v[(pv & 0xFFFFu) * 16 + chunk];
            acc_edge_u4(rv, edup_from_packed(pv), hp, hu);
        }
        j++;
    }
    for (; j + 8 <= end; j += 8) {
        uint4 ea = *(const uint4*)&g_edgep[j];
        uint4 eb = *(const uint4*)&g_edgep[j + 4];
        unsigned p0 = half ? ea.y : ea.x;
        unsigned p1 = half ? ea.w : ea.z;
        unsigned p2 = half ? eb.y : eb.x;
        unsigned p3 = half ? eb.w : eb.z;
        uint4 r0 = g_h16v[(p0 & 0xFFFFu) * 16 + chunk];
        uint4 r1 = g_h16v[(p1 & 0xFFFFu) * 16 + chunk];
        uint4 r2 = g_h16v[(p2 & 0xFFFFu) * 16 + chunk];
        uint4 r3 = g_h16v[(p3 & 0xFFFFu) * 16 + chunk];
        acc_edge_u4(r0, edup_from_packed(p0), hp, hu);
        acc_edge_u4(r1, edup_from_packed(p1), hp, hu);
        acc_edge_u4(r2, edup_from_packed(p2), hp, hu);
        acc_edge_u4(r3, edup_from_packed(p3), hp, hu);
    }
    if (j + 4 <= end) {
        uint4 ea = *(const uint4*)&g_edgep[j];
        unsigned p0 = half ? ea.y : ea.x;
        unsigned p1 = half ? ea.w : ea.z;
        uint4 r0 = g_h16v[(p0 & 0xFFFFu) * 16 + chunk];
        uint4 r1 = g_h16v[(p1 & 0xFFFFu) * 16 + chunk];
        acc_edge_u4(r0, edup_from_packed(p0), hp, hu);
        acc_edge_u4(r1, edup_from_packed(p1), hp, hu);
        j += 4;
    }
    if (j + 2 <= end) {
        uint2 ea = *(const uint2*)&g_edgep[j];
        unsigned p0 = half ? ea.y : ea.x;
        uint4 r0 = g_h16v[(p0 & 0xFFFFu) * 16 + chunk];
        acc_edge_u4(r0, edup_from_packed(p0), hp, hu);
        j += 2;
    }
    if (j < end && half == 0) {
        unsigned pv = g_edgep[j];
        uint4 rv = g_h16v[(pv & 0xFFFFu) * 16 + chunk];
        acc_edge_u4(rv, edup_from_packed(pv), hp, hu);
    }

    #pragma unroll
    for (int q = 0; q < 4; q++) {
        unsigned long long t = __shfl_xor_sync(0xffffffffu, hp[q], 16);
        asm("add.rn.f32x2 %0, %0, %1;" : "+l"(hp[q]) : "l"(t));
        t = __shfl_xor_sync(0xffffffffu, hu[q], 16);
        asm("add.rn.f32x2 %0, %0, %1;" : "+l"(hu[q]) : "l"(t));
    }

    float inv = 1.f / (float)max(deg, 1);
    unsigned long long* accs = half ? hu : hp;
    float* dstp = half ? g_hu : g_hp;
    float2 v0 = u64_to_f2(accs[0]);
    float2 v1 = u64_to_f2(accs[1]);
    float2 v2 = u64_to_f2(accs[2]);
    float2 v3 = u64_to_f2(accs[3]);
    float4 o0 = make_float4(v0.x * inv, v0.y * inv, v1.x * inv, v1.y * inv);
    float4 o1 = make_float4(v2.x * inv, v2.y * inv, v3.x * inv, v3.y * inv);
    ((float4*)dstp)[warp * 32 + chunk * 2]     = o0;
    ((float4*)dstp)[warp * 32 + chunk * 2 + 1] = o1;
}

// ---------------------------------------------------------------------------
// GEMM v2: k-packed FFMA2. BM=32, BN=64, BK=32, 64 threads.
// Thread (ty=tid/8, tx=tid%8): rows ty*4..+3, cols tx + 8c (c=0..7).
// acc[r][c] holds {even-k, odd-k} partial sums; horizontal add at epilogue.
// Double-buffered with register staging (1 barrier per tile).
// ---------------------------------------------------------------------------
#define GBM 32
#define GBN 64
#define GBK 32
#define GKP 36          // GBK + 4 pad (16B-aligned rows, conflict-free)

struct GSm {
    float X[2][GBM][GKP];
    float W[2][GBN][GKP];
};

__device__ __forceinline__ void g_load_tile(
    const float* __restrict__ Xp, int m0, int M, int k0l, int k0w, int n0,
    int tid, float4 xr[4], float4 wr[8])
{
    #pragma unroll
    for (int p = 0; p < 4; p++) {
        int idx = p * 64 + tid;          // 0..255
        int row = idx >> 3;              // 0..31
        int cg  = idx & 7;               // 0..7
        int gr  = m0 + row; if (gr >= M) gr = M - 1;
        xr[p] = *(const float4*)&Xp[gr * F + k0l + cg * 4];
    }
    #pragma unroll
    for (int p = 0; p < 8; p++) {
        int idx = p * 64 + tid;          // 0..511
        int n   = idx >> 3;              // 0..63
        int cg  = idx & 7;               // 0..7
        wr[p] = *(const float4*)&g_W[(n0 + n) * (3 * F) + k0w + cg * 4];
    }
}

__device__ __forceinline__ void g_store_tile(
    GSm& sm, int buf, int tid, const float4 xr[4], const float4 wr[8])
{
    #pragma unroll
    for (int p = 0; p < 4; p++) {
        int idx = p * 64 + tid;
        int row = idx >> 3, cg = idx & 7;
        *(float4*)&sm.X[buf][row][cg * 4] = xr[p];
    }
    #pragma unroll
    for (int p = 0; p < 8; p++) {
        int idx = p * 64 + tid;
        int n = idx >> 3, cg = idx & 7;
        *(float4*)&sm.W[buf][n][cg * 4] = wr[p];
    }
}

__device__ __forceinline__ void g_compute_tile(
    GSm& sm, int buf, int ty, int tx, unsigned long long acc[4][8])
{
    #pragma unroll
    for (int kk = 0; kk < GBK; kk += 4) {
        ulonglong2 a[4];
        #pragma unroll
        for (int r = 0; r < 4; r++)
            a[r] = *(const ulonglong2*)&sm.X[buf][ty * 4 + r][kk];
        ulonglong2 b[8];
        #pragma unroll
        for (int c = 0; c < 8; c++)
            b[c] = *(const ulonglong2*)&sm.W[buf][tx + 8 * c][kk];
        #pragma unroll
        for (int r = 0; r < 4; r++)
            #pragma unroll
            for (int c = 0; c < 8; c++) {
                asm("fma.rn.f32x2 %0, %1, %2, %0;" : "+l"(acc[r][c])
                    : "l"(a[r].x), "l"(b[c].x));
                asm("fma.rn.f32x2 %0, %1, %2, %0;" : "+l"(acc[r][c])
                    : "l"(a[r].y), "l"(b[c].y));
            }
    }
}

// out = h @ A^T + bias   (K tiles 0..3, seg 0 of g_W)
__global__ __launch_bounds__(64) void gemm_h_kernel(
    const float* __restrict__ h, float* __restrict__ out, int M)
{
    __shared__ GSm sm;
    int tid = threadIdx.x, tx = tid & 7, ty = tid >> 3;
    int m0 = blockIdx.x * GBM;
    int n0 = blockIdx.y * GBN;

    unsigned long long acc[4][8];
    #pragma unroll
    for (int r = 0; r < 4; r++)
        #pragma unroll
        for (int c = 0; c < 8; c++) acc[r][c] = 0ull;

    float4 xr[4]; float4 wr[8];
    g_load_tile(h, m0, M, 0, 0, n0, tid, xr, wr);
    g_store_tile(sm, 0, tid, xr, wr);
    __syncthreads();

    int buf = 0;
    for (int t = 0; t < 4; t++) {
        if (t + 1 < 4)
            g_load_tile(h, m0, M, (t + 1) * GBK, (t + 1) * GBK, n0, tid, xr, wr);
        g_compute_tile(sm, buf, ty, tx, acc);
        if (t + 1 < 4)
            g_store_tile(sm, buf ^ 1, tid, xr, wr);
        __syncthreads();
        buf ^= 1;
    }

    #pragma unroll
    for (int r = 0; r < 4; r++) {
        int gr = m0 + ty * 4 + r;
        if (gr < M) {
            #pragma unroll
            for (int c = 0; c < 8; c++) {
                int n = n0 + tx + 8 * c;
                float2 v = u64_to_f2(acc[r][c]);
                out[gr * F + n] = v.x + v.y + g_bias[n];
            }
        }
    }
}

// out += hp @ B^T + hu @ C^T   (K tiles: 4 from hp, 4 from hu; segs 1,2)
__global__ __launch_bounds__(64) void gemm_pu_kernel(
    float* __restrict__ out, int M)
{
    __shared__ GSm sm;
    int tid = threadIdx.x, tx = tid & 7, ty = tid >> 3;
    int m0 = blockIdx.x * GBM;
    int n0 = blockIdx.y * GBN;

    unsigned long long acc[4][8];
    #pragma unroll
    for (int r = 0; r < 4; r++)
        #pragma unroll
        for (int c = 0; c < 8; c++) acc[r][c] = 0ull;

    float4 xr[4]; float4 wr[8];
    g_load_tile(g_hp, m0, M, 0, F, n0, tid, xr, wr);
    g_store_tile(sm, 0, tid, xr, wr);
    __syncthreads();

    int buf = 0;
    for (int t = 0; t < 8; t++) {
        if (t + 1 < 8) {
            int tn = t + 1;
            const float* Xp = (tn < 4) ? g_hp : g_hu;
            g_load_tile(Xp, m0, M, (tn & 3) * GBK, F + tn * GBK, n0,
                        tid, xr, wr);
        }
        g_compute_tile(sm, buf, ty, tx, acc);
        if (t + 1 < 8)
            g_store_tile(sm, buf ^ 1, tid, xr, wr);
        __syncthreads();
        buf ^= 1;
    }

    #pragma unroll
    for (int r = 0; r < 4; r++) {
        int gr = m0 + ty * 4 + r;
        if (gr < M) {
            #pragma unroll
            for (int c = 0; c < 8; c++) {
                int n = n0 + tx + 8 * c;
                float2 v = u64_to_f2(acc[r][c]);
                out[gr * F + n] += v.x + v.y;
            }
        }
    }
}

// ---------------------------------------------------------------------------
extern "C" void kernel_launch(void* const* d_in, const int* in_sizes, int n_in,
                              void* d_out, int out_size) {
    const float* h     = (const float*)d_in[0];
    const float* e     = (const float*)d_in[1];
    const int*   src   = (const int*)d_in[2];
    const int*   dst   = (const int*)d_in[3];
    const float* Ws_w  = (const float*)d_in[4];
    const float* Ws_b  = (const float*)d_in[5];
    const float* Wn_w  = (const float*)d_in[6];
    const float* Wn_b  = (const float*)d_in[7];
    const float* Wu_w  = (const float*)d_in[8];
    const float* Wu_b  = (const float*)d_in[9];
    const float* lin_w = (const float*)d_in[10];
    const float* lin_b = (const float*)d_in[11];
    float* out = (float*)d_out;

    int M = in_sizes[0] / F;
    int E = in_sizes[2];
    if (M > SCAN_N) M = SCAN_N;
    if (E > EDGES_CAP) E = EDGES_CAP;

    int nElem8     = (M * F) / 8;
    int convBlocks = (nElem8 + 255) / 256;
    int histBlocks = (E + 2047) / 2048;
    dim3 gemmGrid((M + GBM - 1) / GBM, F / GBN);

    // Side stream + events (created fresh per call; never destroyed —
    // kernel_launch is invoked only a handful of times).
    cudaStream_t s2;
    cudaStreamCreateWithFlags(&s2, cudaStreamNonBlocking);
    cudaEvent_t evA, evB;
    cudaEventCreateWithFlags(&evA, cudaEventDisableTiming);
    cudaEventCreateWithFlags(&evB, cudaEventDisableTiming);

    // legacy: mega (fuse ∥ convert ∥ hist + embedded scan)
    mega_kernel<<<F + convBlocks + histBlocks, 256>>>(
        lin_w, lin_b, Ws_w, Wn_w, Wu_w, Ws_b, Wn_b, Wu_b,
        h, nElem8, convBlocks, dst, E, histBlocks);
    cudaEventRecord(evA, 0);

    // s2: h @ A^T + bias (needs fused weights from mega)
    cudaStreamWaitEvent(s2, evA, 0);
    gemm_h_kernel<<<gemmGrid, 64, 0, s2>>>(h, out, M);
    cudaEventRecord(evB, s2);

    // legacy: scatter -> agg
    scatter_kernel<<<(E + 2047) / 2048, 256>>>(src, dst, e, E);
    agg_kernel<<<(M + 7) / 8, 256>>>(M);

    // join: accumulate aggregated parts into out
    cudaStreamWaitEvent(0, evB, 0);
    gemm_pu_kernel<<<gemmGrid, 64>>>(out, M);
}